// round 1
// baseline (speedup 1.0000x reference)
#include <cuda_runtime.h>
#include <math.h>

// Problem constants
#define CB   512    // batch
#define CS   120    // encoder seq len
#define CD   216    // feature dim
#define CH   1024   // hidden dim
#define CML  24     // decoder steps

// Step-kernel tiling
#define BM 64
#define BJ 32
#define BK 8
#define TM 8
#define TJ 2
#define NTHREADS ((BM/TM)*(BJ/TJ))   // 128

// Persistent state (device globals: allowed scratch)
__device__ float g_h[2][CB * CH];
__device__ float g_c[CB * CH];
__device__ float g_x[CB * CD];

__global__ void init_state_kernel() {
    int idx = blockIdx.x * blockDim.x + threadIdx.x;
    if (idx < CB * CH) {
        g_h[0][idx] = 0.0f;
        g_c[idx]    = 0.0f;
    }
}

__device__ __forceinline__ float sigf(float x) { return 1.0f / (1.0f + expf(-x)); }

// One LSTM step: gates = [x|h] @ [W_ih|W_hh]^T + (b_ih+b_hh); cell update.
// Each block: BM batch rows x BJ hidden cols x all 4 gates (A tile reused 4x).
// hread = g_h[rd], hwrite = g_h[wr] (ping-pong), c updated in place.
__global__ __launch_bounds__(NTHREADS)
void lstm_step_kernel(const float* __restrict__ xbase, int xstride, int use_gx,
                      int rd, int wr,
                      const float* __restrict__ W_ih, const float* __restrict__ W_hh,
                      const float* __restrict__ b_ih, const float* __restrict__ b_hh)
{
    __shared__ float As[BK][BM];        // A tile, k-major
    __shared__ float Ws[4][BK][BJ];     // W tile per gate

    const int jb = blockIdx.x * BJ;     // hidden-col tile (0..1023)
    const int mb = blockIdx.y * BM;     // batch-row tile
    const int tid = threadIdx.x;
    const int tc = tid & 15;            // j-group (16)
    const int tr = tid >> 4;            // row-group (8)
    const int la_m  = tid >> 1;         // A-loader row
    const int la_k4 = (tid & 1) * 4;    // A-loader k offset
    const int wg = tid >> 5;            // W-loader gate (4)
    const int wj = tid & 31;            // W-loader col (32)

    const float* hread = g_h[rd];
    const float* xb = use_gx ? g_x : xbase;
    const int    xs = use_gx ? CD : xstride;

    float acc[4][TM][TJ];
#pragma unroll
    for (int g = 0; g < 4; ++g)
#pragma unroll
        for (int i = 0; i < TM; ++i)
#pragma unroll
            for (int jj = 0; jj < TJ; ++jj) acc[g][i][jj] = 0.0f;

    // ---------------- phase 1: x contribution (K = CD = 216) ----------------
    {
        const float* aRow = xb + (size_t)(mb + la_m) * xs + la_k4;
        const float* wRow = W_ih + (size_t)(wg * CH + jb + wj) * CD;
#pragma unroll 1
        for (int kb = 0; kb < CD; kb += BK) {
            float4 av = *reinterpret_cast<const float4*>(aRow + kb);
            float4 w0 = *reinterpret_cast<const float4*>(wRow + kb);
            float4 w1 = *reinterpret_cast<const float4*>(wRow + kb + 4);
            As[la_k4 + 0][la_m] = av.x; As[la_k4 + 1][la_m] = av.y;
            As[la_k4 + 2][la_m] = av.z; As[la_k4 + 3][la_m] = av.w;
            Ws[wg][0][wj] = w0.x; Ws[wg][1][wj] = w0.y;
            Ws[wg][2][wj] = w0.z; Ws[wg][3][wj] = w0.w;
            Ws[wg][4][wj] = w1.x; Ws[wg][5][wj] = w1.y;
            Ws[wg][6][wj] = w1.z; Ws[wg][7][wj] = w1.w;
            __syncthreads();
#pragma unroll
            for (int kk = 0; kk < BK; ++kk) {
                float a[TM], w[4][TJ];
#pragma unroll
                for (int i = 0; i < TM; ++i) a[i] = As[kk][tr * TM + i];
#pragma unroll
                for (int g = 0; g < 4; ++g)
#pragma unroll
                    for (int jj = 0; jj < TJ; ++jj) w[g][jj] = Ws[g][kk][tc * TJ + jj];
#pragma unroll
                for (int g = 0; g < 4; ++g)
#pragma unroll
                    for (int i = 0; i < TM; ++i)
#pragma unroll
                        for (int jj = 0; jj < TJ; ++jj)
                            acc[g][i][jj] += a[i] * w[g][jj];
            }
            __syncthreads();
        }
    }

    // ---------------- phase 2: h contribution (K = CH = 1024) ----------------
    {
        const float* aRow = hread + (size_t)(mb + la_m) * CH + la_k4;
        const float* wRow = W_hh + (size_t)(wg * CH + jb + wj) * CH;
#pragma unroll 1
        for (int kb = 0; kb < CH; kb += BK) {
            float4 av = *reinterpret_cast<const float4*>(aRow + kb);
            float4 w0 = *reinterpret_cast<const float4*>(wRow + kb);
            float4 w1 = *reinterpret_cast<const float4*>(wRow + kb + 4);
            As[la_k4 + 0][la_m] = av.x; As[la_k4 + 1][la_m] = av.y;
            As[la_k4 + 2][la_m] = av.z; As[la_k4 + 3][la_m] = av.w;
            Ws[wg][0][wj] = w0.x; Ws[wg][1][wj] = w0.y;
            Ws[wg][2][wj] = w0.z; Ws[wg][3][wj] = w0.w;
            Ws[wg][4][wj] = w1.x; Ws[wg][5][wj] = w1.y;
            Ws[wg][6][wj] = w1.z; Ws[wg][7][wj] = w1.w;
            __syncthreads();
#pragma unroll
            for (int kk = 0; kk < BK; ++kk) {
                float a[TM], w[4][TJ];
#pragma unroll
                for (int i = 0; i < TM; ++i) a[i] = As[kk][tr * TM + i];
#pragma unroll
                for (int g = 0; g < 4; ++g)
#pragma unroll
                    for (int jj = 0; jj < TJ; ++jj) w[g][jj] = Ws[g][kk][tc * TJ + jj];
#pragma unroll
                for (int g = 0; g < 4; ++g)
#pragma unroll
                    for (int i = 0; i < TM; ++i)
#pragma unroll
                        for (int jj = 0; jj < TJ; ++jj)
                            acc[g][i][jj] += a[i] * w[g][jj];
            }
            __syncthreads();
        }
    }

    // ---------------- epilogue: LSTM cell ----------------
    float bias[4][TJ];
#pragma unroll
    for (int g = 0; g < 4; ++g)
#pragma unroll
        for (int jj = 0; jj < TJ; ++jj) {
            int j = jb + tc * TJ + jj;
            bias[g][jj] = b_ih[g * CH + j] + b_hh[g * CH + j];
        }

    float* hwrite = g_h[wr];
#pragma unroll
    for (int i = 0; i < TM; ++i) {
        int row = mb + tr * TM + i;
#pragma unroll
        for (int jj = 0; jj < TJ; ++jj) {
            int j = jb + tc * TJ + jj;
            float gi = acc[0][i][jj] + bias[0][jj];
            float gf = acc[1][i][jj] + bias[1][jj];
            float gg = acc[2][i][jj] + bias[2][jj];
            float go = acc[3][i][jj] + bias[3][jj];
            size_t off = (size_t)row * CH + j;
            float c_old = g_c[off];
            float c_new = sigf(gf) * c_old + sigf(gi) * tanhf(gg);
            float h_new = sigf(go) * tanhf(c_new);
            g_c[off] = c_new;
            hwrite[off] = h_new;
        }
    }
}

// Decoder projection: y = h @ W_out^T + b_out ; write to output slice and g_x.
// Block = 8 batch rows x all 216 cols; 216 threads; grid = 64.
__global__ void proj_kernel(int hbuf,
                            const float* __restrict__ W_out,
                            const float* __restrict__ b_out,
                            float* __restrict__ outp)  // d_out + step*CD
{
    __shared__ float hs[8][CH];   // 32 KB
    const float* h = g_h[hbuf];
    int bb0 = blockIdx.x * 8;
    int tid = threadIdx.x;

    for (int idx = tid; idx < 8 * CH; idx += blockDim.x) {
        int r = idx >> 10;
        int c = idx & (CH - 1);
        hs[r][c] = h[(size_t)(bb0 + r) * CH + c];
    }
    __syncthreads();

    int d = tid;  // 0..215
    float acc[8];
#pragma unroll
    for (int bb = 0; bb < 8; ++bb) acc[bb] = 0.0f;

    const float4* wrow = reinterpret_cast<const float4*>(W_out + (size_t)d * CH);
#pragma unroll 4
    for (int k4 = 0; k4 < CH / 4; ++k4) {
        float4 w = wrow[k4];
#pragma unroll
        for (int bb = 0; bb < 8; ++bb) {
            float4 hv = *reinterpret_cast<const float4*>(&hs[bb][k4 * 4]);
            acc[bb] += hv.x * w.x + hv.y * w.y + hv.z * w.z + hv.w * w.w;
        }
    }

    float bo = b_out[d];
#pragma unroll
    for (int bb = 0; bb < 8; ++bb) {
        float y = acc[bb] + bo;
        outp[(size_t)(bb0 + bb) * CML * CD + d] = y;   // out[(b*ML+s)*D + d]
        g_x[(size_t)(bb0 + bb) * CD + d] = y;          // next decoder input
    }
}

extern "C" void kernel_launch(void* const* d_in, const int* in_sizes, int n_in,
                              void* d_out, int out_size)
{
    (void)in_sizes; (void)n_in; (void)out_size;
    const float* src   = (const float*)d_in[0];  // (B, S, D)
    const float* W_ih  = (const float*)d_in[1];  // (4H, D)
    const float* W_hh  = (const float*)d_in[2];  // (4H, H)
    const float* b_ih  = (const float*)d_in[3];  // (4H)
    const float* b_hh  = (const float*)d_in[4];  // (4H)
    const float* W_out = (const float*)d_in[5];  // (D, H)
    const float* b_out = (const float*)d_in[6];  // (D)
    float* out = (float*)d_out;                  // (B, ML, D)

    init_state_kernel<<<(CB * CH + 255) / 256, 256>>>();

    dim3 sgrid(CH / BJ, CB / BM);   // 32 x 8 = 256 blocks
    dim3 sblock(NTHREADS);

    int p = 0;
    // Encoder: 120 teacher-forced steps
    for (int t = 0; t < CS; ++t) {
        lstm_step_kernel<<<sgrid, sblock>>>(src + (size_t)t * CD, CS * CD, /*use_gx=*/0,
                                            /*rd=*/p, /*wr=*/p ^ 1,
                                            W_ih, W_hh, b_ih, b_hh);
        p ^= 1;
    }
    // Decoder: 24 autoregressive steps starting from src[:, S-1, :]
    for (int s = 0; s < CML; ++s) {
        if (s == 0) {
            lstm_step_kernel<<<sgrid, sblock>>>(src + (size_t)(CS - 1) * CD, CS * CD, 0,
                                                p, p ^ 1, W_ih, W_hh, b_ih, b_hh);
        } else {
            lstm_step_kernel<<<sgrid, sblock>>>(nullptr, 0, /*use_gx=*/1,
                                                p, p ^ 1, W_ih, W_hh, b_ih, b_hh);
        }
        proj_kernel<<<CB / 8, CD>>>(p ^ 1, W_out, b_out, out + (size_t)s * CD);
        p ^= 1;
    }
}

// round 3
// speedup vs baseline: 3.0433x; 3.0433x over previous
#include <cuda_runtime.h>
#include <cuda_bf16.h>
#include <math.h>
#include <stdint.h>

#define CB   512
#define CS   120
#define CD   216
#define CH   1024
#define CML  24

#define NCH   20        // 4 x-chunks (K padded 216->256) + 16 h-chunks, K=64 each
#define NCH_X 4
#define NT    32        // N tiles of 128 (4 gates x 32 j)
#define XSTR  256       // padded x-plane stride

// SMEM: A tile (64 rows x 64 k, hi+lo bf16, swizzled) then gate-exchange buffer
#define SM_A_BYTES 16384
#define SG_STRIDE  36
#define SM_SG_BYTES (4*64*SG_STRIDE*4)   // 36864
#define SMEM_STEP  (SM_A_BYTES + SM_SG_BYTES)

// ---------------- device globals (sanctioned scratch) ----------------
__device__ uint2 g_W[(size_t)NT * 4 * NCH * 4 * 2 * 32 * 4];          // 21 MB frag-layout weights
__device__ __nv_bfloat16 g_src_hi[(size_t)CS * CB * XSTR];            // 31.5 MB
__device__ __nv_bfloat16 g_src_lo[(size_t)CS * CB * XSTR];
__device__ __nv_bfloat16 g_xd_hi[(size_t)CB * XSTR];
__device__ __nv_bfloat16 g_xd_lo[(size_t)CB * XSTR];
__device__ __nv_bfloat16 g_h_hi[2][(size_t)CB * CH];
__device__ __nv_bfloat16 g_h_lo[2][(size_t)CB * CH];
__device__ float g_c[(size_t)CB * CH];
__device__ float g_bias[4 * CH];

// ---------------- helpers ----------------
__device__ __forceinline__ uint32_t smem_u32(const void* p) {
    uint32_t a;
    asm("{ .reg .u64 t; cvta.to.shared.u64 t, %1; cvt.u32.u64 %0, t; }" : "=r"(a) : "l"(p));
    return a;
}
__device__ __forceinline__ void ldsm4(uint32_t* r, uint32_t addr) {
    asm volatile("ldmatrix.sync.aligned.m8n8.x4.shared.b16 {%0,%1,%2,%3}, [%4];"
        : "=r"(r[0]), "=r"(r[1]), "=r"(r[2]), "=r"(r[3]) : "r"(addr));
}
__device__ __forceinline__ void mma16816(float* d, const uint32_t* a, uint32_t b0, uint32_t b1) {
    asm volatile("mma.sync.aligned.m16n8k16.row.col.f32.bf16.bf16.f32 "
        "{%0,%1,%2,%3}, {%4,%5,%6,%7}, {%8,%9}, {%0,%1,%2,%3};"
        : "+f"(d[0]), "+f"(d[1]), "+f"(d[2]), "+f"(d[3])
        : "r"(a[0]), "r"(a[1]), "r"(a[2]), "r"(a[3]), "r"(b0), "r"(b1));
}
__device__ __forceinline__ float sigf(float x) { return 1.0f / (1.0f + __expf(-x)); }
__device__ __forceinline__ uint32_t pack_bf2(float a, float b) {
    return (uint32_t)__bfloat16_as_ushort(__float2bfloat16(a)) |
           ((uint32_t)__bfloat16_as_ushort(__float2bfloat16(b)) << 16);
}

// ---------------- init ----------------
__global__ void init_kernel(const float* __restrict__ b_ih, const float* __restrict__ b_hh) {
    int idx = blockIdx.x * blockDim.x + threadIdx.x;
    if (idx < CB * CH) {
        g_c[idx] = 0.0f;
        g_h_hi[0][idx] = __float2bfloat16(0.0f);
        g_h_lo[0][idx] = __float2bfloat16(0.0f);
    }
    if (idx < CB * XSTR) {
        g_xd_hi[idx] = __float2bfloat16(0.0f);
        g_xd_lo[idx] = __float2bfloat16(0.0f);
    }
    if (idx < 4 * CH) g_bias[idx] = b_ih[idx] + b_hh[idx];
}

// split src (B,S,D) fp32 -> planes [t][row][XSTR] bf16 hi/lo (zero-padded)
__global__ void src_split_kernel(const float* __restrict__ src) {
    size_t idx = (size_t)blockIdx.x * blockDim.x + threadIdx.x;
    if (idx >= (size_t)CS * CB * XSTR) return;
    int c = (int)(idx & (XSTR - 1));
    int r = (int)((idx >> 8) & (CB - 1));
    int t = (int)(idx >> 17);
    float v = (c < CD) ? src[((size_t)r * CS + t) * CD + c] : 0.0f;
    __nv_bfloat16 hi = __float2bfloat16(v);
    __nv_bfloat16 lo = __float2bfloat16(v - __bfloat162float(hi));
    g_src_hi[idx] = hi;
    g_src_lo[idx] = lo;
}

// weights -> B-fragment layout, hi/lo, gate-interleaved N reorder
__global__ void prep_w_kernel(const float* __restrict__ W_ih, const float* __restrict__ W_hh) {
    int s = blockIdx.x * blockDim.x + threadIdx.x;
    const int TOT = NT * 4 * NCH * 4 * 32 * 4;   // 1,310,720
    if (s >= TOT) return;
    int nblk = s & 3;
    int lane = (s >> 2) & 31;
    int k16  = (s >> 7) & 3;
    int rest = s >> 9;
    int ch = rest % NCH; rest /= NCH;
    int wc = rest & 3;
    int nt = rest >> 2;

    int j = nt * 32 + nblk * 8 + (lane >> 2);
    int R = wc * CH + j;                     // weight row (gate-major)
    int k0 = k16 * 16 + (lane & 3) * 2;

    float v[4];
    if (ch < NCH_X) {
        int kb = ch * 64 + k0;
        int ks[4] = {kb, kb + 1, kb + 8, kb + 9};
#pragma unroll
        for (int q = 0; q < 4; ++q)
            v[q] = (ks[q] < CD) ? W_ih[(size_t)R * CD + ks[q]] : 0.0f;
    } else {
        int kb = (ch - NCH_X) * 64 + k0;
        const float* wr = W_hh + (size_t)R * CH + kb;
        v[0] = wr[0]; v[1] = wr[1]; v[2] = wr[8]; v[3] = wr[9];
    }
    float hi[4], lo[4];
#pragma unroll
    for (int q = 0; q < 4; ++q) {
        hi[q] = __bfloat162float(__float2bfloat16(v[q]));
        lo[q] = v[q] - hi[q];
    }
    size_t d0 = ((((size_t)(nt * 4 + wc) * NCH + ch) * 4 + k16) * 2) * 128 + lane * 4 + nblk;
    g_W[d0]       = make_uint2(pack_bf2(hi[0], hi[1]), pack_bf2(hi[2], hi[3]));
    g_W[d0 + 128] = make_uint2(pack_bf2(lo[0], lo[1]), pack_bf2(lo[2], lo[3]));
}

// ---------------- fused LSTM step (mma.sync) ----------------
__global__ __launch_bounds__(256, 2)
void lstm_step(int use_xd, int t, int rd, int wr)
{
    extern __shared__ char smem[];
    float* sg = (float*)(smem + SM_A_BYTES);
    const uint32_t sma = smem_u32(smem);

    const int tid = threadIdx.x;
    const int lane = tid & 31;
    const int w = tid >> 5;
    const int wm = w & 1;          // 2 warp rows (32 each)
    const int wn = w >> 1;         // 4 warp cols = gate
    const int nt = blockIdx.x;
    const int mb = blockIdx.y * 64;

    const __nv_bfloat16* xhi;
    const __nv_bfloat16* xlo;
    if (use_xd) { xhi = g_xd_hi; xlo = g_xd_lo; }
    else { xhi = g_src_hi + (size_t)t * CB * XSTR; xlo = g_src_lo + (size_t)t * CB * XSTR; }
    const __nv_bfloat16* hhi = g_h_hi[rd];
    const __nv_bfloat16* hlo = g_h_lo[rd];

    // A-copy thread mapping
    const int cp_plane = tid >> 7;           // 0=hi,1=lo
    const int cp_r = (tid >> 1) & 63;
    const int cp_cb = (tid & 1) * 4;
    uint32_t cp_dst[4];
#pragma unroll
    for (int q = 0; q < 4; ++q)
        cp_dst[q] = (uint32_t)(cp_plane * 8192 + cp_r * 128 + (((cp_cb + q) ^ (cp_r & 7)) << 4));

    // ldmatrix row bases
    int lrow[2];
#pragma unroll
    for (int m2 = 0; m2 < 2; ++m2) lrow[m2] = wm * 32 + m2 * 16 + (lane & 15);
    const int lc_half = lane >> 4;

    float acc[2][4][4];
#pragma unroll
    for (int m2 = 0; m2 < 2; ++m2)
#pragma unroll
        for (int nb = 0; nb < 4; ++nb)
#pragma unroll
            for (int e = 0; e < 4; ++e) acc[m2][nb][e] = 0.0f;

    auto load_chunk = [&](int ch, uint4* a) {
        const __nv_bfloat16* base;
        int stride;
        if (ch < NCH_X) {
            base = (cp_plane ? xlo : xhi) + ch * 64;
            stride = XSTR;
        } else {
            base = (cp_plane ? hlo : hhi) + (ch - NCH_X) * 64;
            stride = CH;
        }
        const uint4* p = (const uint4*)(base + (size_t)(mb + cp_r) * stride + cp_cb * 8);
#pragma unroll
        for (int q = 0; q < 4; ++q) a[q] = p[q];
    };

    uint4 areg[4];
    load_chunk(0, areg);

    const int nt4wn20 = (nt * 4 + wn) * NCH;
    const uint4* wbase = (const uint4*)g_W;

#pragma unroll 1
    for (int ch = 0; ch < NCH; ++ch) {
#pragma unroll
        for (int q = 0; q < 4; ++q) *(uint4*)(smem + cp_dst[q]) = areg[q];
        __syncthreads();
        if (ch + 1 < NCH) load_chunk(ch + 1, areg);

        const uint4* wq = wbase + ((size_t)(nt4wn20 + ch) * 4) * 128 + lane * 2;
        uint4 chA = wq[0], chB = wq[1], clA = wq[64], clB = wq[65];

#pragma unroll
        for (int k16 = 0; k16 < 4; ++k16) {
            uint4 nhA, nhB, nlA, nlB;
            if (k16 < 3) {
                const uint4* wn_ = wq + (size_t)(k16 + 1) * 128;
                nhA = wn_[0]; nhB = wn_[1]; nlA = wn_[64]; nlB = wn_[65];
            }
            uint32_t ah[2][4], al[2][4];
#pragma unroll
            for (int m2 = 0; m2 < 2; ++m2) {
                uint32_t cidx = (uint32_t)(k16 * 2 + lc_half);
                uint32_t byte = (uint32_t)lrow[m2] * 128 + ((cidx ^ ((uint32_t)lrow[m2] & 7)) << 4);
                ldsm4(ah[m2], sma + byte);
                ldsm4(al[m2], sma + 8192 + byte);
            }
            uint32_t bh0[4] = {chA.x, chA.z, chB.x, chB.z};
            uint32_t bh1[4] = {chA.y, chA.w, chB.y, chB.w};
            uint32_t bl0[4] = {clA.x, clA.z, clB.x, clB.z};
            uint32_t bl1[4] = {clA.y, clA.w, clB.y, clB.w};
#pragma unroll
            for (int m2 = 0; m2 < 2; ++m2)
#pragma unroll
                for (int nb = 0; nb < 4; ++nb) {
                    mma16816(acc[m2][nb], ah[m2], bh0[nb], bh1[nb]);
                    mma16816(acc[m2][nb], al[m2], bh0[nb], bh1[nb]);
                    mma16816(acc[m2][nb], ah[m2], bl0[nb], bl1[nb]);
                }
            if (k16 < 3) { chA = nhA; chB = nhB; clA = nlA; clB = nlB; }
        }
        __syncthreads();
    }

    // gates -> smem exchange
#pragma unroll
    for (int m2 = 0; m2 < 2; ++m2)
#pragma unroll
        for (int nb = 0; nb < 4; ++nb) {
            int r0 = wm * 32 + m2 * 16 + (lane >> 2);
            int jj = nb * 8 + (lane & 3) * 2;
            float* p0 = &sg[((size_t)(wn * 64 + r0)) * SG_STRIDE + jj];
            p0[0] = acc[m2][nb][0]; p0[1] = acc[m2][nb][1];
            float* p1 = p0 + 8 * SG_STRIDE;
            p1[0] = acc[m2][nb][2]; p1[1] = acc[m2][nb][3];
        }
    __syncthreads();

    // cell update
    {
        int row = tid >> 2;
        int jjb = (tid & 3) * 8;
        int jcol = nt * 32 + jjb;
        size_t off = (size_t)(mb + row) * CH + jcol;

        float gv[4][8];
#pragma unroll
        for (int g = 0; g < 4; ++g) {
            const float* p = &sg[((size_t)(g * 64 + row)) * SG_STRIDE + jjb];
#pragma unroll
            for (int e = 0; e < 8; ++e) gv[g][e] = p[e] + g_bias[g * CH + jcol + e];
        }
        float4 cA = *(const float4*)(g_c + off);
        float4 cB = *(const float4*)(g_c + off + 4);
        float cold[8] = {cA.x, cA.y, cA.z, cA.w, cB.x, cB.y, cB.z, cB.w};
        float cn[8], hn[8];
#pragma unroll
        for (int e = 0; e < 8; ++e) {
            float ci = sigf(gv[0][e]);
            float cf = sigf(gv[1][e]);
            float cg = tanhf(gv[2][e]);
            float co = sigf(gv[3][e]);
            cn[e] = cf * cold[e] + ci * cg;
            hn[e] = co * tanhf(cn[e]);
        }
        *(float4*)(g_c + off)     = make_float4(cn[0], cn[1], cn[2], cn[3]);
        *(float4*)(g_c + off + 4) = make_float4(cn[4], cn[5], cn[6], cn[7]);

        uint32_t ph[4], pl[4];
#pragma unroll
        for (int e2 = 0; e2 < 4; ++e2) {
            float a = hn[e2 * 2], b = hn[e2 * 2 + 1];
            __nv_bfloat16 ah_ = __float2bfloat16(a), bh_ = __float2bfloat16(b);
            ph[e2] = (uint32_t)__bfloat16_as_ushort(ah_) |
                     ((uint32_t)__bfloat16_as_ushort(bh_) << 16);
            pl[e2] = pack_bf2(a - __bfloat162float(ah_), b - __bfloat162float(bh_));
        }
        *(uint4*)(&g_h_hi[wr][off]) = make_uint4(ph[0], ph[1], ph[2], ph[3]);
        *(uint4*)(&g_h_lo[wr][off]) = make_uint4(pl[0], pl[1], pl[2], pl[3]);
    }
}

// ---------------- decoder projection ----------------
__global__ void proj_kernel(int hbuf,
                            const float* __restrict__ W_out,
                            const float* __restrict__ b_out,
                            float* __restrict__ outp)
{
    __shared__ float hs[8][CH];
    const __nv_bfloat16* phi = g_h_hi[hbuf];
    const __nv_bfloat16* plo = g_h_lo[hbuf];
    int bb0 = blockIdx.x * 8;
    int tid = threadIdx.x;

    for (int idx = tid; idx < 8 * CH; idx += blockDim.x) {
        int r = idx >> 10, c = idx & (CH - 1);
        size_t o = (size_t)(bb0 + r) * CH + c;
        hs[r][c] = __bfloat162float(phi[o]) + __bfloat162float(plo[o]);
    }
    __syncthreads();

    int d = tid;
    if (d < CD) {
        float acc[8];
#pragma unroll
        for (int bb = 0; bb < 8; ++bb) acc[bb] = 0.0f;
        const float4* wrow = reinterpret_cast<const float4*>(W_out + (size_t)d * CH);
#pragma unroll 4
        for (int k4 = 0; k4 < CH / 4; ++k4) {
            float4 wv = wrow[k4];
#pragma unroll
            for (int bb = 0; bb < 8; ++bb) {
                float4 hv = *reinterpret_cast<const float4*>(&hs[bb][k4 * 4]);
                acc[bb] += hv.x * wv.x + hv.y * wv.y + hv.z * wv.z + hv.w * wv.w;
            }
        }
        float bo = b_out[d];
#pragma unroll
        for (int bb = 0; bb < 8; ++bb) {
            float y = acc[bb] + bo;
            outp[(size_t)(bb0 + bb) * CML * CD + d] = y;
            __nv_bfloat16 hi = __float2bfloat16(y);
            size_t o = (size_t)(bb0 + bb) * XSTR + d;
            g_xd_hi[o] = hi;
            g_xd_lo[o] = __float2bfloat16(y - __bfloat162float(hi));
        }
    }
}

extern "C" void kernel_launch(void* const* d_in, const int* in_sizes, int n_in,
                              void* d_out, int out_size)
{
    (void)in_sizes; (void)n_in; (void)out_size;
    const float* src   = (const float*)d_in[0];
    const float* W_ih  = (const float*)d_in[1];
    const float* W_hh  = (const float*)d_in[2];
    const float* b_ih  = (const float*)d_in[3];
    const float* b_hh  = (const float*)d_in[4];
    const float* W_out = (const float*)d_in[5];
    const float* b_out = (const float*)d_in[6];
    float* out = (float*)d_out;

    cudaFuncSetAttribute(lstm_step, cudaFuncAttributeMaxDynamicSharedMemorySize, SMEM_STEP);

    init_kernel<<<(CB * CH + 255) / 256, 256>>>(b_ih, b_hh);
    {
        size_t tot = (size_t)CS * CB * XSTR;
        src_split_kernel<<<(unsigned)((tot + 255) / 256), 256>>>(src);
    }
    {
        int tot = NT * 4 * NCH * 4 * 32 * 4;
        prep_w_kernel<<<(tot + 255) / 256, 256>>>(W_ih, W_hh);
    }

    dim3 sgrid(NT, CB / 64);   // 32 x 8 = 256 CTAs
    int p = 0;
    for (int t = 0; t < CS; ++t) {
        lstm_step<<<sgrid, 256, SMEM_STEP>>>(0, t, p, p ^ 1);
        p ^= 1;
    }
    for (int s = 0; s < CML; ++s) {
        if (s == 0) lstm_step<<<sgrid, 256, SMEM_STEP>>>(0, CS - 1, p, p ^ 1);
        else        lstm_step<<<sgrid, 256, SMEM_STEP>>>(1, 0, p, p ^ 1);
        proj_kernel<<<CB / 8, 224>>>(p ^ 1, W_out, b_out, out + (size_t)s * CD);
        p ^= 1;
    }
}

// round 4
// speedup vs baseline: 4.6455x; 1.5265x over previous
#include <cuda_runtime.h>
#include <cuda_fp16.h>
#include <math.h>
#include <stdint.h>

#define CB   512
#define CS   120
#define CD   216
#define CH   1024
#define CML  24

#define NCH   20        // 4 x-chunks (K 216->256 padded) + 16 h-chunks, K=64 each
#define NCH_X 4
#define NT    32        // N tiles of 128 cols (4 gates x 32 j)
#define MT    128       // M tile per CTA
#define XSTR  256       // padded x-plane stride

// per-chunk SMEM buffer: A hi 16KB | A lo 16KB | W 16KB
#define BUF_STRIDE 49152
#define SMEM_STEP  (2 * BUF_STRIDE)   // 96KB (epilogue sg reuses it)
#define SGJ 33                        // gate-exchange j stride (floats)

// ---------------- device globals ----------------
__device__ __align__(16) __half g_Wimg[(size_t)NT * NCH * 8192];       // 10.5MB swizzled fp16 W
__device__ __align__(16) __half g_src_hi[(size_t)CS * CB * XSTR];
__device__ __align__(16) __half g_src_lo[(size_t)CS * CB * XSTR];
__device__ __align__(16) __half g_xd_hi[(size_t)CB * XSTR];
__device__ __align__(16) __half g_xd_lo[(size_t)CB * XSTR];
__device__ __align__(16) __half g_h_hi[2][(size_t)CB * CH];
__device__ __align__(16) __half g_h_lo[2][(size_t)CB * CH];
__device__ float g_c[(size_t)CB * CH];
__device__ float g_bias[4 * CH];

// ---------------- helpers ----------------
__device__ __forceinline__ uint32_t smem_u32(const void* p) {
    uint32_t a;
    asm("{ .reg .u64 t; cvta.to.shared.u64 t, %1; cvt.u32.u64 %0, t; }" : "=r"(a) : "l"(p));
    return a;
}
__device__ __forceinline__ void ldsm4(uint32_t* r, uint32_t addr) {
    asm volatile("ldmatrix.sync.aligned.m8n8.x4.shared.b16 {%0,%1,%2,%3}, [%4];"
        : "=r"(r[0]), "=r"(r[1]), "=r"(r[2]), "=r"(r[3]) : "r"(addr));
}
__device__ __forceinline__ void mma_h(float* d, const uint32_t* a, uint32_t b0, uint32_t b1) {
    asm volatile("mma.sync.aligned.m16n8k16.row.col.f32.f16.f16.f32 "
        "{%0,%1,%2,%3}, {%4,%5,%6,%7}, {%8,%9}, {%0,%1,%2,%3};"
        : "+f"(d[0]), "+f"(d[1]), "+f"(d[2]), "+f"(d[3])
        : "r"(a[0]), "r"(a[1]), "r"(a[2]), "r"(a[3]), "r"(b0), "r"(b1));
}
#define CP16(dst, src) \
    asm volatile("cp.async.cg.shared.global [%0], [%1], 16;" :: "r"(dst), "l"(src))
#define CP_COMMIT() asm volatile("cp.async.commit_group;" ::: "memory")
#define CP_WAIT(n)  asm volatile("cp.async.wait_group %0;" :: "n"(n) : "memory")

__device__ __forceinline__ float sigf(float x) { return 1.0f / (1.0f + __expf(-x)); }

// ---------------- init / precompute ----------------
__global__ void init_kernel(const float* __restrict__ b_ih, const float* __restrict__ b_hh) {
    int idx = blockIdx.x * blockDim.x + threadIdx.x;
    if (idx < CB * CH) {
        g_c[idx] = 0.0f;
        g_h_hi[0][idx] = __float2half_rn(0.0f);
        g_h_lo[0][idx] = __float2half_rn(0.0f);
    }
    if (idx < CB * XSTR) {
        g_xd_hi[idx] = __float2half_rn(0.0f);
        g_xd_lo[idx] = __float2half_rn(0.0f);
    }
    if (idx < 4 * CH) g_bias[idx] = b_ih[idx] + b_hh[idx];
}

__global__ void src_split_kernel(const float* __restrict__ src) {
    size_t idx = (size_t)blockIdx.x * blockDim.x + threadIdx.x;
    if (idx >= (size_t)CS * CB * XSTR) return;
    int c = (int)(idx & (XSTR - 1));
    int r = (int)((idx >> 8) & (CB - 1));
    int t = (int)(idx >> 17);
    float v = (c < CD) ? src[((size_t)r * CS + t) * CD + c] : 0.0f;
    __half hi = __float2half_rn(v);
    __half lo = __float2half_rn(v - __half2float(hi));
    g_src_hi[idx] = hi;
    g_src_lo[idx] = lo;
}

// W -> pre-swizzled fp16 tile image: [nt][ch] tiles of 128 n-rows x 64 k
__global__ void prep_w_kernel(const float* __restrict__ W_ih, const float* __restrict__ W_hh) {
    int idx = blockIdx.x * blockDim.x + threadIdx.x;
    const int TOT = NT * NCH * 128 * 64;
    if (idx >= TOT) return;
    int k = idx & 63;
    int r = (idx >> 6) & 127;
    int ch = (idx >> 13) % NCH;
    int nt = idx / (NCH * 8192);
    int gate = r >> 5, jj = r & 31;
    int R = gate * CH + nt * 32 + jj;
    float v;
    if (ch < NCH_X) {
        int kg = ch * 64 + k;
        v = (kg < CD) ? W_ih[(size_t)R * CD + kg] : 0.0f;
    } else {
        v = W_hh[(size_t)R * CH + (ch - NCH_X) * 64 + k];
    }
    size_t dest = (size_t)(nt * NCH + ch) * 8192 + r * 64 + (((k >> 3) ^ (r & 7)) << 3) + (k & 7);
    g_Wimg[dest] = __float2half_rn(v);
}

// ---------------- fused LSTM step ----------------
__global__ __launch_bounds__(256, 1)
void lstm_step(int use_xd, int t, int rd, int wr)
{
    extern __shared__ char smem[];
    const uint32_t sb = smem_u32(smem);
    const int tid = threadIdx.x;
    const int lane = tid & 31;
    const int w = tid >> 5;
    const int wm = w & 1;          // 2 warp rows (64 each)
    const int wn = w >> 1;         // 4 warp cols = gate
    const int nt = blockIdx.x;
    const int mb = blockIdx.y * MT;

    const __half* xhi;
    const __half* xlo;
    if (use_xd) { xhi = g_xd_hi; xlo = g_xd_lo; }
    else { xhi = g_src_hi + (size_t)t * CB * XSTR; xlo = g_src_lo + (size_t)t * CB * XSTR; }
    const __half* hhi = g_h_hi[rd];
    const __half* hlo = g_h_lo[rd];

    // per-thread cp.async A mapping (8 granules/thread; plane,row,chunk fixed)
    int ar[8], acb[8], apl[8];
    uint32_t aoff[8];
#pragma unroll
    for (int it = 0; it < 8; ++it) {
        int idx = tid + it * 256;
        apl[it] = idx >> 10;
        int rem = idx & 1023;
        ar[it]  = rem >> 3;
        acb[it] = rem & 7;
        aoff[it] = (uint32_t)(apl[it] * 16384 + ar[it] * 128 + ((acb[it] ^ (ar[it] & 7)) << 4));
    }

    auto issue_chunk = [&](int ch, uint32_t buf) {
        const char* wsrc = (const char*)(g_Wimg + (size_t)(nt * NCH + ch) * 8192);
#pragma unroll
        for (int it = 0; it < 4; ++it) {
            int g = tid + it * 256;
            CP16(buf + 32768 + g * 16, wsrc + g * 16);
        }
        const __half *p0, *p1;
        int stride, koff;
        if (ch < NCH_X) { p0 = xhi; p1 = xlo; stride = XSTR; koff = ch * 64; }
        else            { p0 = hhi; p1 = hlo; stride = CH;   koff = (ch - NCH_X) * 64; }
#pragma unroll
        for (int it = 0; it < 8; ++it) {
            const __half* sp = (apl[it] ? p1 : p0) +
                               (size_t)(mb + ar[it]) * stride + koff + acb[it] * 8;
            CP16(buf + aoff[it], sp);
        }
    };

    // ldmatrix base patterns
    uint32_t abase[4]; int amask[4];
#pragma unroll
    for (int mg = 0; mg < 4; ++mg) {
        int rr = wm * 64 + mg * 16 + (lane & 15);
        abase[mg] = (uint32_t)(rr * 128);
        amask[mg] = rr & 7;
    }
    const int akc_half = lane >> 4;
    uint32_t wbse[2]; int wmask[2];
#pragma unroll
    for (int p16 = 0; p16 < 2; ++p16) {
        int rr = wn * 32 + p16 * 16 + (lane & 7) + ((lane >> 4) << 3);
        wbse[p16] = (uint32_t)(32768 + rr * 128);
        wmask[p16] = rr & 7;
    }
    const int wkc_par = (lane >> 3) & 1;

    float acc[4][4][4];
#pragma unroll
    for (int mg = 0; mg < 4; ++mg)
#pragma unroll
        for (int nb = 0; nb < 4; ++nb)
#pragma unroll
            for (int e = 0; e < 4; ++e) acc[mg][nb][e] = 0.0f;

    issue_chunk(0, sb);
    CP_COMMIT();

#pragma unroll 1
    for (int ch = 0; ch < NCH; ++ch) {
        const uint32_t buf = sb + (uint32_t)(ch & 1) * BUF_STRIDE;
        if (ch + 1 < NCH) {
            issue_chunk(ch + 1, sb + (uint32_t)((ch + 1) & 1) * BUF_STRIDE);
            CP_COMMIT();
            CP_WAIT(1);
        } else {
            CP_WAIT(0);
        }
        __syncthreads();

#pragma unroll
        for (int k16 = 0; k16 < 4; ++k16) {
            uint32_t ah[4][4], al[4][4], wf[2][4];
            const uint32_t kcA = (uint32_t)(2 * k16 + akc_half);
            const uint32_t kcW = (uint32_t)(2 * k16 + wkc_par);
#pragma unroll
            for (int p16 = 0; p16 < 2; ++p16)
                ldsm4(wf[p16], buf + wbse[p16] + ((kcW ^ (uint32_t)wmask[p16]) << 4));
#pragma unroll
            for (int mg = 0; mg < 4; ++mg) {
                uint32_t ad = buf + abase[mg] + ((kcA ^ (uint32_t)amask[mg]) << 4);
                ldsm4(ah[mg], ad);
                ldsm4(al[mg], ad + 16384);
            }
#pragma unroll
            for (int mg = 0; mg < 4; ++mg)
#pragma unroll
                for (int p16 = 0; p16 < 2; ++p16) {
                    mma_h(acc[mg][2 * p16 + 0], ah[mg], wf[p16][0], wf[p16][1]);
                    mma_h(acc[mg][2 * p16 + 0], al[mg], wf[p16][0], wf[p16][1]);
                    mma_h(acc[mg][2 * p16 + 1], ah[mg], wf[p16][2], wf[p16][3]);
                    mma_h(acc[mg][2 * p16 + 1], al[mg], wf[p16][2], wf[p16][3]);
                }
        }
        __syncthreads();
    }

    // gate exchange (reuse smem)
    float* sg = (float*)smem;
#pragma unroll
    for (int mg = 0; mg < 4; ++mg)
#pragma unroll
        for (int nb = 0; nb < 4; ++nb) {
            int r0 = wm * 64 + mg * 16 + (lane >> 2);
            int jj = nb * 8 + (lane & 3) * 2;
            float* p0 = &sg[((size_t)(wn * 128 + r0)) * SGJ + jj];
            p0[0] = acc[mg][nb][0]; p0[1] = acc[mg][nb][1];
            float* p1 = p0 + 8 * SGJ;
            p1[0] = acc[mg][nb][2]; p1[1] = acc[mg][nb][3];
        }
    __syncthreads();

    // cell update: 512 units, 2 per thread
    __half* hwhi = g_h_hi[wr];
    __half* hwlo = g_h_lo[wr];
#pragma unroll
    for (int u = 0; u < 2; ++u) {
        int uid = tid + u * 256;
        int row = uid >> 2;
        int j0 = (uid & 3) * 8;
        int jcol = nt * 32 + j0;
        size_t off = (size_t)(mb + row) * CH + jcol;

        float gv[4][8];
#pragma unroll
        for (int g = 0; g < 4; ++g) {
            const float* p = &sg[((size_t)(g * 128 + row)) * SGJ + j0];
#pragma unroll
            for (int e = 0; e < 8; ++e) gv[g][e] = p[e] + g_bias[g * CH + jcol + e];
        }
        float4 cA = *(const float4*)(g_c + off);
        float4 cB = *(const float4*)(g_c + off + 4);
        float cold[8] = {cA.x, cA.y, cA.z, cA.w, cB.x, cB.y, cB.z, cB.w};
        float cn[8], hn[8];
#pragma unroll
        for (int e = 0; e < 8; ++e) {
            float ci = sigf(gv[0][e]);
            float cf = sigf(gv[1][e]);
            float cg = tanhf(gv[2][e]);
            float co = sigf(gv[3][e]);
            cn[e] = cf * cold[e] + ci * cg;
            hn[e] = co * tanhf(cn[e]);
        }
        *(float4*)(g_c + off)     = make_float4(cn[0], cn[1], cn[2], cn[3]);
        *(float4*)(g_c + off + 4) = make_float4(cn[4], cn[5], cn[6], cn[7]);

        uint32_t ph[4], pl[4];
#pragma unroll
        for (int e2 = 0; e2 < 4; ++e2) {
            __half ha = __float2half_rn(hn[e2 * 2]);
            __half hb = __float2half_rn(hn[e2 * 2 + 1]);
            ph[e2] = (uint32_t)__half_as_ushort(ha) | ((uint32_t)__half_as_ushort(hb) << 16);
            __half la = __float2half_rn(hn[e2 * 2] - __half2float(ha));
            __half lb = __float2half_rn(hn[e2 * 2 + 1] - __half2float(hb));
            pl[e2] = (uint32_t)__half_as_ushort(la) | ((uint32_t)__half_as_ushort(lb) << 16);
        }
        *(uint4*)(hwhi + off) = make_uint4(ph[0], ph[1], ph[2], ph[3]);
        *(uint4*)(hwlo + off) = make_uint4(pl[0], pl[1], pl[2], pl[3]);
    }
}

// ---------------- decoder projection ----------------
// grid (27 d-groups, 64 batch-groups), 256 threads; warp w -> d = dg*8+w, 8 rows.
__global__ __launch_bounds__(256)
void proj_kernel(int hbuf,
                 const float* __restrict__ W_out,
                 const float* __restrict__ b_out,
                 float* __restrict__ outp)
{
    int lane = threadIdx.x & 31;
    int w = threadIdx.x >> 5;
    int d = blockIdx.x * 8 + w;
    int r0 = blockIdx.y * 8;
    const __half* phi = g_h_hi[hbuf];
    const __half* plo = g_h_lo[hbuf];
    int k0 = lane * 32;

    float wv[32];
    {
        const float4* wp = (const float4*)(W_out + (size_t)d * CH + k0);
#pragma unroll
        for (int q = 0; q < 8; ++q) {
            float4 f = wp[q];
            wv[q * 4 + 0] = f.x; wv[q * 4 + 1] = f.y; wv[q * 4 + 2] = f.z; wv[q * 4 + 3] = f.w;
        }
    }
    float acc[8];
#pragma unroll
    for (int r = 0; r < 8; ++r) {
        size_t ho = (size_t)(r0 + r) * CH + k0;
        const uint4* hp = (const uint4*)(phi + ho);
        const uint4* lp = (const uint4*)(plo + ho);
        float s = 0.0f;
#pragma unroll
        for (int q = 0; q < 4; ++q) {
            uint4 hv = hp[q], lv = lp[q];
            const __half2* h2 = (const __half2*)&hv;
            const __half2* l2 = (const __half2*)&lv;
#pragma unroll
            for (int e = 0; e < 4; ++e) {
                float2 a = __half22float2(h2[e]);
                float2 b = __half22float2(l2[e]);
                int kk = q * 8 + e * 2;
                s += (a.x + b.x) * wv[kk] + (a.y + b.y) * wv[kk + 1];
            }
        }
        acc[r] = s;
    }
#pragma unroll
    for (int r = 0; r < 8; ++r) {
#pragma unroll
        for (int off = 16; off > 0; off >>= 1)
            acc[r] += __shfl_xor_sync(0xFFFFFFFFu, acc[r], off);
    }
    if (lane == 0) {
        float bo = b_out[d];
#pragma unroll
        for (int r = 0; r < 8; ++r) {
            float y = acc[r] + bo;
            int row = r0 + r;
            outp[(size_t)row * CML * CD + d] = y;
            __half hi = __float2half_rn(y);
            size_t o = (size_t)row * XSTR + d;
            g_xd_hi[o] = hi;
            g_xd_lo[o] = __float2half_rn(y - __half2float(hi));
        }
    }
}

extern "C" void kernel_launch(void* const* d_in, const int* in_sizes, int n_in,
                              void* d_out, int out_size)
{
    (void)in_sizes; (void)n_in; (void)out_size;
    const float* src   = (const float*)d_in[0];
    const float* W_ih  = (const float*)d_in[1];
    const float* W_hh  = (const float*)d_in[2];
    const float* b_ih  = (const float*)d_in[3];
    const float* b_hh  = (const float*)d_in[4];
    const float* W_out = (const float*)d_in[5];
    const float* b_out = (const float*)d_in[6];
    float* out = (float*)d_out;

    static int once = 0;
    if (!once) {
        cudaFuncSetAttribute(lstm_step, cudaFuncAttributeMaxDynamicSharedMemorySize, SMEM_STEP);
        once = 1;
    }

    init_kernel<<<(CB * CH + 255) / 256, 256>>>(b_ih, b_hh);
    {
        size_t tot = (size_t)CS * CB * XSTR;
        src_split_kernel<<<(unsigned)((tot + 255) / 256), 256>>>(src);
    }
    {
        int tot = NT * NCH * 128 * 64;
        prep_w_kernel<<<(tot + 255) / 256, 256>>>(W_ih, W_hh);
    }

    dim3 sgrid(NT, CB / MT);   // 32 x 4 = 128 CTAs
    dim3 pgrid(27, CB / 8);    // 27 x 64

    int p = 0;
    for (int t = 0; t < CS; ++t) {
        lstm_step<<<sgrid, 256, SMEM_STEP>>>(0, t, p, p ^ 1);
        p ^= 1;
    }
    for (int s = 0; s < CML; ++s) {
        if (s == 0) lstm_step<<<sgrid, 256, SMEM_STEP>>>(0, CS - 1, p, p ^ 1);
        else        lstm_step<<<sgrid, 256, SMEM_STEP>>>(1, 0, p, p ^ 1);
        proj_kernel<<<pgrid, 256>>>(p ^ 1, W_out, b_out, out + (size_t)s * CD);
        p ^= 1;
    }
}

// round 5
// speedup vs baseline: 6.6819x; 1.4383x over previous
#include <cuda_runtime.h>
#include <cuda_fp16.h>
#include <math.h>
#include <stdint.h>

#define CB   512
#define CS   120
#define CD   216
#define CH   1024
#define CML  24

#define NCH   20        // 4 x-chunks (K 216->256 padded) + 16 h-chunks, K=64 each
#define NCH_X 4
#define NT    32        // N tiles of 128 cols (4 gates x 32 j)
#define MT    128       // M tile per CTA
#define XSTR  256       // padded x-plane stride

// per-chunk SMEM: A 16KB | W 16KB ; double buffered = 64KB; epilogue sg = 67.6KB
#define BUF_STRIDE 32768
#define SGJ 33
#define SMEM_STEP  (4 * 128 * SGJ * 4)   // 67584 >= 65536

// ---------------- device globals ----------------
__device__ __align__(16) __half g_Wimg[(size_t)NT * NCH * 8192];   // 10.5MB swizzled fp16 W
__device__ __align__(16) __half g_src[(size_t)CS * CB * XSTR];     // fp16 x planes
__device__ __align__(16) __half g_xd[(size_t)CB * XSTR];
__device__ __align__(16) __half g_h[2][(size_t)CB * CH];
__device__ float g_c[(size_t)CB * CH];
__device__ float g_bias[4 * CH];

// ---------------- helpers ----------------
__device__ __forceinline__ uint32_t smem_u32(const void* p) {
    uint32_t a;
    asm("{ .reg .u64 t; cvta.to.shared.u64 t, %1; cvt.u32.u64 %0, t; }" : "=r"(a) : "l"(p));
    return a;
}
__device__ __forceinline__ void ldsm4(uint32_t* r, uint32_t addr) {
    asm volatile("ldmatrix.sync.aligned.m8n8.x4.shared.b16 {%0,%1,%2,%3}, [%4];"
        : "=r"(r[0]), "=r"(r[1]), "=r"(r[2]), "=r"(r[3]) : "r"(addr));
}
__device__ __forceinline__ void mma_h(float* d, const uint32_t* a, uint32_t b0, uint32_t b1) {
    asm volatile("mma.sync.aligned.m16n8k16.row.col.f32.f16.f16.f32 "
        "{%0,%1,%2,%3}, {%4,%5,%6,%7}, {%8,%9}, {%0,%1,%2,%3};"
        : "+f"(d[0]), "+f"(d[1]), "+f"(d[2]), "+f"(d[3])
        : "r"(a[0]), "r"(a[1]), "r"(a[2]), "r"(a[3]), "r"(b0), "r"(b1));
}
#define CP16(dst, src) \
    asm volatile("cp.async.cg.shared.global [%0], [%1], 16;" :: "r"(dst), "l"(src))
#define CP_COMMIT() asm volatile("cp.async.commit_group;" ::: "memory")
#define CP_WAIT(n)  asm volatile("cp.async.wait_group %0;" :: "n"(n) : "memory")

__device__ __forceinline__ float sigf(float x) { return 1.0f / (1.0f + __expf(-x)); }

// ---------------- init / precompute ----------------
__global__ void init_kernel(const float* __restrict__ b_ih, const float* __restrict__ b_hh) {
    int idx = blockIdx.x * blockDim.x + threadIdx.x;
    if (idx < CB * CH) {
        g_c[idx] = 0.0f;
        g_h[0][idx] = __float2half_rn(0.0f);
    }
    if (idx < CB * XSTR) g_xd[idx] = __float2half_rn(0.0f);
    if (idx < 4 * CH) g_bias[idx] = b_ih[idx] + b_hh[idx];
}

__global__ void src_split_kernel(const float* __restrict__ src) {
    size_t idx = (size_t)blockIdx.x * blockDim.x + threadIdx.x;
    if (idx >= (size_t)CS * CB * XSTR) return;
    int c = (int)(idx & (XSTR - 1));
    int r = (int)((idx >> 8) & (CB - 1));
    int t = (int)(idx >> 17);
    float v = (c < CD) ? src[((size_t)r * CS + t) * CD + c] : 0.0f;
    g_src[idx] = __float2half_rn(v);
}

// W -> pre-swizzled fp16 tile image: [nt][ch] tiles of 128 n-rows x 64 k
__global__ void prep_w_kernel(const float* __restrict__ W_ih, const float* __restrict__ W_hh) {
    int idx = blockIdx.x * blockDim.x + threadIdx.x;
    const int TOT = NT * NCH * 128 * 64;
    if (idx >= TOT) return;
    int k = idx & 63;
    int r = (idx >> 6) & 127;
    int ch = (idx >> 13) % NCH;
    int nt = idx / (NCH * 8192);
    int gate = r >> 5, jj = r & 31;
    int R = gate * CH + nt * 32 + jj;
    float v;
    if (ch < NCH_X) {
        int kg = ch * 64 + k;
        v = (kg < CD) ? W_ih[(size_t)R * CD + kg] : 0.0f;
    } else {
        v = W_hh[(size_t)R * CH + (ch - NCH_X) * 64 + k];
    }
    size_t dest = (size_t)(nt * NCH + ch) * 8192 + r * 64 + (((k >> 3) ^ (r & 7)) << 3) + (k & 7);
    g_Wimg[dest] = __float2half_rn(v);
}

// ---------------- fused LSTM step: 512 threads, 16 warps, warp tile 32x32 ----------------
__global__ __launch_bounds__(512, 1)
void lstm_step(int use_xd, int t, int rd, int wr)
{
    extern __shared__ char smem[];
    const uint32_t sb = smem_u32(smem);
    const int tid = threadIdx.x;
    const int lane = tid & 31;
    const int w = tid >> 5;
    const int wm = w & 3;          // 4 row groups of 32
    const int wn = w >> 2;         // 4 gate groups of 32 cols
    const int nt = blockIdx.x;
    const int mb = blockIdx.y * MT;

    const __half* xp = use_xd ? g_xd : (g_src + (size_t)t * CB * XSTR);
    const __half* hp = g_h[rd];

    // cp.async A mapping: 1024 granules of 16B, 2 per thread
    int ar[2], acb[2];
    uint32_t aoff[2];
#pragma unroll
    for (int it = 0; it < 2; ++it) {
        int idx = tid + it * 512;
        ar[it]  = idx >> 3;
        acb[it] = idx & 7;
        aoff[it] = (uint32_t)(ar[it] * 128 + ((acb[it] ^ (ar[it] & 7)) << 4));
    }

    auto issue_chunk = [&](int ch, uint32_t buf) {
        const char* wsrc = (const char*)(g_Wimg + (size_t)(nt * NCH + ch) * 8192);
#pragma unroll
        for (int it = 0; it < 2; ++it) {
            int g = tid + it * 512;
            CP16(buf + 16384 + g * 16, wsrc + g * 16);
        }
        const __half* p0;
        int stride, koff;
        if (ch < NCH_X) { p0 = xp; stride = XSTR; koff = ch * 64; }
        else            { p0 = hp; stride = CH;   koff = (ch - NCH_X) * 64; }
#pragma unroll
        for (int it = 0; it < 2; ++it) {
            const __half* sp = p0 + (size_t)(mb + ar[it]) * stride + koff + acb[it] * 8;
            CP16(buf + aoff[it], sp);
        }
    };

    // ldmatrix base patterns
    uint32_t abase[2]; int amask[2];
#pragma unroll
    for (int mg = 0; mg < 2; ++mg) {
        int rr = wm * 32 + mg * 16 + (lane & 15);
        abase[mg] = (uint32_t)(rr * 128);
        amask[mg] = rr & 7;
    }
    const int akc_half = lane >> 4;
    uint32_t wbse[2]; int wmask[2];
#pragma unroll
    for (int p16 = 0; p16 < 2; ++p16) {
        int rr = wn * 32 + p16 * 16 + (lane & 7) + ((lane >> 4) << 3);
        wbse[p16] = (uint32_t)(16384 + rr * 128);
        wmask[p16] = rr & 7;
    }
    const int wkc_par = (lane >> 3) & 1;

    float acc[2][4][4];
#pragma unroll
    for (int mg = 0; mg < 2; ++mg)
#pragma unroll
        for (int nb = 0; nb < 4; ++nb)
#pragma unroll
            for (int e = 0; e < 4; ++e) acc[mg][nb][e] = 0.0f;

    issue_chunk(0, sb);
    CP_COMMIT();

#pragma unroll 1
    for (int ch = 0; ch < NCH; ++ch) {
        const uint32_t buf = sb + (uint32_t)(ch & 1) * BUF_STRIDE;
        if (ch + 1 < NCH) {
            issue_chunk(ch + 1, sb + (uint32_t)((ch + 1) & 1) * BUF_STRIDE);
            CP_COMMIT();
            CP_WAIT(1);
        } else {
            CP_WAIT(0);
        }
        __syncthreads();

#pragma unroll
        for (int k16 = 0; k16 < 4; ++k16) {
            uint32_t ah[2][4], wf[2][4];
            const uint32_t kcA = (uint32_t)(2 * k16 + akc_half);
            const uint32_t kcW = (uint32_t)(2 * k16 + wkc_par);
#pragma unroll
            for (int p16 = 0; p16 < 2; ++p16)
                ldsm4(wf[p16], buf + wbse[p16] + ((kcW ^ (uint32_t)wmask[p16]) << 4));
#pragma unroll
            for (int mg = 0; mg < 2; ++mg)
                ldsm4(ah[mg], buf + abase[mg] + ((kcA ^ (uint32_t)amask[mg]) << 4));
#pragma unroll
            for (int mg = 0; mg < 2; ++mg)
#pragma unroll
                for (int p16 = 0; p16 < 2; ++p16) {
                    mma_h(acc[mg][2 * p16 + 0], ah[mg], wf[p16][0], wf[p16][1]);
                    mma_h(acc[mg][2 * p16 + 1], ah[mg], wf[p16][2], wf[p16][3]);
                }
        }
        __syncthreads();
    }

    // gate exchange (reuse smem)
    float* sg = (float*)smem;
#pragma unroll
    for (int mg = 0; mg < 2; ++mg)
#pragma unroll
        for (int nb = 0; nb < 4; ++nb) {
            int r0 = wm * 32 + mg * 16 + (lane >> 2);
            int jj = nb * 8 + (lane & 3) * 2;
            float* p0 = &sg[((size_t)(wn * 128 + r0)) * SGJ + jj];
            p0[0] = acc[mg][nb][0]; p0[1] = acc[mg][nb][1];
            float* p1 = p0 + 8 * SGJ;
            p1[0] = acc[mg][nb][2]; p1[1] = acc[mg][nb][3];
        }
    __syncthreads();

    // cell update: 128 rows x 32 j -> 512 threads x (1 row, 8 j)
    {
        int row = tid >> 2;
        int j0 = (tid & 3) * 8;
        int jcol = nt * 32 + j0;
        size_t off = (size_t)(mb + row) * CH + jcol;

        float gv[4][8];
#pragma unroll
        for (int g = 0; g < 4; ++g) {
            const float* p = &sg[((size_t)(g * 128 + row)) * SGJ + j0];
#pragma unroll
            for (int e = 0; e < 8; ++e) gv[g][e] = p[e] + g_bias[g * CH + jcol + e];
        }
        float4 cA = *(const float4*)(g_c + off);
        float4 cB = *(const float4*)(g_c + off + 4);
        float cold[8] = {cA.x, cA.y, cA.z, cA.w, cB.x, cB.y, cB.z, cB.w};
        float cn[8], hn[8];
#pragma unroll
        for (int e = 0; e < 8; ++e) {
            float ci = sigf(gv[0][e]);
            float cf = sigf(gv[1][e]);
            float cg = tanhf(gv[2][e]);
            float co = sigf(gv[3][e]);
            cn[e] = cf * cold[e] + ci * cg;
            hn[e] = co * tanhf(cn[e]);
        }
        *(float4*)(g_c + off)     = make_float4(cn[0], cn[1], cn[2], cn[3]);
        *(float4*)(g_c + off + 4) = make_float4(cn[4], cn[5], cn[6], cn[7]);

        uint32_t ph[4];
#pragma unroll
        for (int e2 = 0; e2 < 4; ++e2) {
            __half ha = __float2half_rn(hn[e2 * 2]);
            __half hb = __float2half_rn(hn[e2 * 2 + 1]);
            ph[e2] = (uint32_t)__half_as_ushort(ha) | ((uint32_t)__half_as_ushort(hb) << 16);
        }
        *(uint4*)(&g_h[wr][off]) = make_uint4(ph[0], ph[1], ph[2], ph[3]);
    }
}

// ---------------- decoder projection ----------------
__global__ __launch_bounds__(256)
void proj_kernel(int hbuf,
                 const float* __restrict__ W_out,
                 const float* __restrict__ b_out,
                 float* __restrict__ outp)
{
    int lane = threadIdx.x & 31;
    int w = threadIdx.x >> 5;
    int d = blockIdx.x * 8 + w;
    int r0 = blockIdx.y * 8;
    const __half* hp = g_h[hbuf];
    int k0 = lane * 32;

    float wv[32];
    {
        const float4* wp = (const float4*)(W_out + (size_t)d * CH + k0);
#pragma unroll
        for (int q = 0; q < 8; ++q) {
            float4 f = wp[q];
            wv[q * 4 + 0] = f.x; wv[q * 4 + 1] = f.y; wv[q * 4 + 2] = f.z; wv[q * 4 + 3] = f.w;
        }
    }
    float acc[8];
#pragma unroll
    for (int r = 0; r < 8; ++r) {
        const uint4* hq = (const uint4*)(hp + (size_t)(r0 + r) * CH + k0);
        float s = 0.0f;
#pragma unroll
        for (int q = 0; q < 4; ++q) {
            uint4 hv = hq[q];
            const __half2* h2 = (const __half2*)&hv;
#pragma unroll
            for (int e = 0; e < 4; ++e) {
                float2 a = __half22float2(h2[e]);
                int kk = q * 8 + e * 2;
                s += a.x * wv[kk] + a.y * wv[kk + 1];
            }
        }
        acc[r] = s;
    }
#pragma unroll
    for (int r = 0; r < 8; ++r) {
#pragma unroll
        for (int off = 16; off > 0; off >>= 1)
            acc[r] += __shfl_xor_sync(0xFFFFFFFFu, acc[r], off);
    }
    if (lane == 0) {
        float bo = b_out[d];
#pragma unroll
        for (int r = 0; r < 8; ++r) {
            float y = acc[r] + bo;
            int row = r0 + r;
            outp[(size_t)row * CML * CD + d] = y;
            g_xd[(size_t)row * XSTR + d] = __float2half_rn(y);
        }
    }
}

extern "C" void kernel_launch(void* const* d_in, const int* in_sizes, int n_in,
                              void* d_out, int out_size)
{
    (void)in_sizes; (void)n_in; (void)out_size;
    const float* src   = (const float*)d_in[0];
    const float* W_ih  = (const float*)d_in[1];
    const float* W_hh  = (const float*)d_in[2];
    const float* b_ih  = (const float*)d_in[3];
    const float* b_hh  = (const float*)d_in[4];
    const float* W_out = (const float*)d_in[5];
    const float* b_out = (const float*)d_in[6];
    float* out = (float*)d_out;

    static int once = 0;
    if (!once) {
        cudaFuncSetAttribute(lstm_step, cudaFuncAttributeMaxDynamicSharedMemorySize, SMEM_STEP);
        once = 1;
    }

    init_kernel<<<(CB * CH + 255) / 256, 256>>>(b_ih, b_hh);
    {
        size_t tot = (size_t)CS * CB * XSTR;
        src_split_kernel<<<(unsigned)((tot + 255) / 256), 256>>>(src);
    }
    {
        int tot = NT * NCH * 128 * 64;
        prep_w_kernel<<<(tot + 255) / 256, 256>>>(W_ih, W_hh);
    }

    dim3 sgrid(NT, CB / MT);   // 32 x 4 = 128 CTAs
    dim3 pgrid(27, CB / 8);    // 27 x 64

    int p = 0;
    for (int t = 0; t < CS; ++t) {
        lstm_step<<<sgrid, 512, SMEM_STEP>>>(0, t, p, p ^ 1);
        p ^= 1;
    }
    for (int s = 0; s < CML; ++s) {
        if (s == 0) lstm_step<<<sgrid, 512, SMEM_STEP>>>(0, CS - 1, p, p ^ 1);
        else        lstm_step<<<sgrid, 512, SMEM_STEP>>>(1, 0, p, p ^ 1);
        proj_kernel<<<pgrid, 256>>>(p ^ 1, W_out, b_out, out + (size_t)s * CD);
        p ^= 1;
    }
}

// round 6
// speedup vs baseline: 7.1662x; 1.0725x over previous
#include <cuda_runtime.h>
#include <cuda_fp16.h>
#include <math.h>
#include <stdint.h>

#define CB   512
#define CS   120
#define CD   216
#define CH   1024
#define CML  24

#define NCH   20        // 4 x-chunks (K 216->256 padded) + 16 h-chunks, K=64 each
#define NCH_X 4
#define NT    32        // N tiles of 128 cols (4 gates x 32 j)
#define MT    64        // M tile per CTA
#define XSTR  256       // padded x-plane stride

// stage: A 8KB | W 16KB ; 3 stages
#define BUF_STRIDE 24576
#define NSTAGE 3
#define SGJ 33
#define SMEM_STEP (NSTAGE * BUF_STRIDE)   // 73728 (epilogue sg: 4*64*33*4=33792 fits)

// ---------------- device globals ----------------
__device__ __align__(16) __half g_Wimg[(size_t)NT * NCH * 8192];   // 10.5MB swizzled fp16 W
__device__ __align__(16) __half g_src[(size_t)CS * CB * XSTR];
__device__ __align__(16) __half g_xd[(size_t)CB * XSTR];
__device__ __align__(16) __half g_h[2][(size_t)CB * CH];
__device__ float g_c[(size_t)CB * CH];
__device__ float g_bias[4 * CH];

// ---------------- helpers ----------------
__device__ __forceinline__ uint32_t smem_u32(const void* p) {
    uint32_t a;
    asm("{ .reg .u64 t; cvta.to.shared.u64 t, %1; cvt.u32.u64 %0, t; }" : "=r"(a) : "l"(p));
    return a;
}
__device__ __forceinline__ void ldsm4(uint32_t* r, uint32_t addr) {
    asm volatile("ldmatrix.sync.aligned.m8n8.x4.shared.b16 {%0,%1,%2,%3}, [%4];"
        : "=r"(r[0]), "=r"(r[1]), "=r"(r[2]), "=r"(r[3]) : "r"(addr));
}
__device__ __forceinline__ void mma_h(float* d, const uint32_t* a, uint32_t b0, uint32_t b1) {
    asm volatile("mma.sync.aligned.m16n8k16.row.col.f32.f16.f16.f32 "
        "{%0,%1,%2,%3}, {%4,%5,%6,%7}, {%8,%9}, {%0,%1,%2,%3};"
        : "+f"(d[0]), "+f"(d[1]), "+f"(d[2]), "+f"(d[3])
        : "r"(a[0]), "r"(a[1]), "r"(a[2]), "r"(a[3]), "r"(b0), "r"(b1));
}
#define CP16(dst, src) \
    asm volatile("cp.async.cg.shared.global [%0], [%1], 16;" :: "r"(dst), "l"(src))
#define CP_COMMIT() asm volatile("cp.async.commit_group;" ::: "memory")
#define CP_WAIT(n)  asm volatile("cp.async.wait_group %0;" :: "n"(n) : "memory")

__device__ __forceinline__ float sigf(float x) { return 1.0f / (1.0f + __expf(-x)); }

// ---------------- init / precompute ----------------
__global__ void init_kernel(const float* __restrict__ b_ih, const float* __restrict__ b_hh) {
    int idx = blockIdx.x * blockDim.x + threadIdx.x;
    if (idx < CB * CH) {
        g_c[idx] = 0.0f;
        g_h[0][idx] = __float2half_rn(0.0f);
    }
    if (idx < CB * XSTR) g_xd[idx] = __float2half_rn(0.0f);
    if (idx < 4 * CH) g_bias[idx] = b_ih[idx] + b_hh[idx];
}

__global__ void src_split_kernel(const float* __restrict__ src) {
    size_t idx = (size_t)blockIdx.x * blockDim.x + threadIdx.x;
    if (idx >= (size_t)CS * CB * XSTR) return;
    int c = (int)(idx & (XSTR - 1));
    int r = (int)((idx >> 8) & (CB - 1));
    int t = (int)(idx >> 17);
    float v = (c < CD) ? src[((size_t)r * CS + t) * CD + c] : 0.0f;
    g_src[idx] = __float2half_rn(v);
}

// W -> pre-swizzled fp16 tile image: [nt][ch] tiles of 128 n-rows x 64 k
__global__ void prep_w_kernel(const float* __restrict__ W_ih, const float* __restrict__ W_hh) {
    int idx = blockIdx.x * blockDim.x + threadIdx.x;
    const int TOT = NT * NCH * 128 * 64;
    if (idx >= TOT) return;
    int k = idx & 63;
    int r = (idx >> 6) & 127;
    int ch = (idx >> 13) % NCH;
    int nt = idx / (NCH * 8192);
    int gate = r >> 5, jj = r & 31;
    int R = gate * CH + nt * 32 + jj;
    float v;
    if (ch < NCH_X) {
        int kg = ch * 64 + k;
        v = (kg < CD) ? W_ih[(size_t)R * CD + kg] : 0.0f;
    } else {
        v = W_hh[(size_t)R * CH + (ch - NCH_X) * 64 + k];
    }
    size_t dest = (size_t)(nt * NCH + ch) * 8192 + r * 64 + (((k >> 3) ^ (r & 7)) << 3) + (k & 7);
    g_Wimg[dest] = __float2half_rn(v);
}

// ---------------- fused LSTM step: 256 threads, 8 warps, warp tile 32x32 ----------------
__global__ __launch_bounds__(256, 2)
void lstm_step(int use_xd, int t, int rd, int wr)
{
    extern __shared__ char smem[];
    const uint32_t sb = smem_u32(smem);
    const int tid = threadIdx.x;
    const int lane = tid & 31;
    const int w = tid >> 5;
    const int wm = w & 1;          // 2 row groups of 32
    const int wn = w >> 1;         // 4 gate groups of 32 cols
    const int nt = blockIdx.x;
    const int mb = blockIdx.y * MT;

    const __half* xp = use_xd ? g_xd : (g_src + (size_t)t * CB * XSTR);
    const __half* hp = g_h[rd];

    // cp.async A mapping: 512 granules of 16B, 2 per thread (A region 8KB)
    int ar[2], acb[2];
    uint32_t aoff[2];
#pragma unroll
    for (int it = 0; it < 2; ++it) {
        int idx = tid + it * 256;
        ar[it]  = idx >> 3;        // 0..63
        acb[it] = idx & 7;
        aoff[it] = (uint32_t)(ar[it] * 128 + ((acb[it] ^ (ar[it] & 7)) << 4));
    }

    auto issue_chunk = [&](int ch, uint32_t buf) {
        const char* wsrc = (const char*)(g_Wimg + (size_t)(nt * NCH + ch) * 8192);
#pragma unroll
        for (int it = 0; it < 4; ++it) {
            int g = tid + it * 256;
            CP16(buf + 8192 + g * 16, wsrc + g * 16);
        }
        const __half* p0;
        int stride, koff;
        if (ch < NCH_X) { p0 = xp; stride = XSTR; koff = ch * 64; }
        else            { p0 = hp; stride = CH;   koff = (ch - NCH_X) * 64; }
#pragma unroll
        for (int it = 0; it < 2; ++it) {
            const __half* sp = p0 + (size_t)(mb + ar[it]) * stride + koff + acb[it] * 8;
            CP16(buf + aoff[it], sp);
        }
    };

    // ldmatrix base patterns
    uint32_t abase[2]; int amask[2];
#pragma unroll
    for (int mg = 0; mg < 2; ++mg) {
        int rr = wm * 32 + mg * 16 + (lane & 15);
        abase[mg] = (uint32_t)(rr * 128);
        amask[mg] = rr & 7;
    }
    const int akc_half = lane >> 4;
    uint32_t wbse[2]; int wmask[2];
#pragma unroll
    for (int p16 = 0; p16 < 2; ++p16) {
        int rr = wn * 32 + p16 * 16 + (lane & 7) + ((lane >> 4) << 3);
        wbse[p16] = (uint32_t)(8192 + rr * 128);
        wmask[p16] = rr & 7;
    }
    const int wkc_par = (lane >> 3) & 1;

    float acc[2][4][4];
#pragma unroll
    for (int mg = 0; mg < 2; ++mg)
#pragma unroll
        for (int nb = 0; nb < 4; ++nb)
#pragma unroll
            for (int e = 0; e < 4; ++e) acc[mg][nb][e] = 0.0f;

    issue_chunk(0, sb);
    CP_COMMIT();
    issue_chunk(1, sb + BUF_STRIDE);
    CP_COMMIT();

    int stage = 0;
#pragma unroll 1
    for (int ch = 0; ch < NCH; ++ch) {
        const uint32_t buf = sb + (uint32_t)stage * BUF_STRIDE;
        if (ch == NCH - 1) { CP_WAIT(0); } else { CP_WAIT(1); }
        __syncthreads();
        if (ch + 2 < NCH) {
            int ns = stage + 2; if (ns >= NSTAGE) ns -= NSTAGE;
            issue_chunk(ch + 2, sb + (uint32_t)ns * BUF_STRIDE);
            CP_COMMIT();
        }

#pragma unroll
        for (int k16 = 0; k16 < 4; ++k16) {
            uint32_t ah[2][4], wf[2][4];
            const uint32_t kcA = (uint32_t)(2 * k16 + akc_half);
            const uint32_t kcW = (uint32_t)(2 * k16 + wkc_par);
#pragma unroll
            for (int p16 = 0; p16 < 2; ++p16)
                ldsm4(wf[p16], buf + wbse[p16] + ((kcW ^ (uint32_t)wmask[p16]) << 4));
#pragma unroll
            for (int mg = 0; mg < 2; ++mg)
                ldsm4(ah[mg], buf + abase[mg] + ((kcA ^ (uint32_t)amask[mg]) << 4));
#pragma unroll
            for (int mg = 0; mg < 2; ++mg)
#pragma unroll
                for (int p16 = 0; p16 < 2; ++p16) {
                    mma_h(acc[mg][2 * p16 + 0], ah[mg], wf[p16][0], wf[p16][1]);
                    mma_h(acc[mg][2 * p16 + 1], ah[mg], wf[p16][2], wf[p16][3]);
                }
        }
        if (++stage >= NSTAGE) stage = 0;
    }
    __syncthreads();   // all consumption done before sg overwrite

    // gate exchange (reuse smem): sg[4 gates * 64 rows][SGJ]
    float* sg = (float*)smem;
#pragma unroll
    for (int mg = 0; mg < 2; ++mg)
#pragma unroll
        for (int nb = 0; nb < 4; ++nb) {
            int r0 = wm * 32 + mg * 16 + (lane >> 2);
            int jj = nb * 8 + (lane & 3) * 2;
            float* p0 = &sg[((size_t)(wn * 64 + r0)) * SGJ + jj];
            p0[0] = acc[mg][nb][0]; p0[1] = acc[mg][nb][1];
            float* p1 = p0 + 8 * SGJ;
            p1[0] = acc[mg][nb][2]; p1[1] = acc[mg][nb][3];
        }
    __syncthreads();

    // cell update: 64 rows x 32 j -> 256 threads x (1 row, 8 j)
    {
        int row = tid >> 2;
        int j0 = (tid & 3) * 8;
        int jcol = nt * 32 + j0;
        size_t off = (size_t)(mb + row) * CH + jcol;

        float gv[4][8];
#pragma unroll
        for (int g = 0; g < 4; ++g) {
            const float* p = &sg[((size_t)(g * 64 + row)) * SGJ + j0];
#pragma unroll
            for (int e = 0; e < 8; ++e) gv[g][e] = p[e] + g_bias[g * CH + jcol + e];
        }
        float4 cA = *(const float4*)(g_c + off);
        float4 cB = *(const float4*)(g_c + off + 4);
        float cold[8] = {cA.x, cA.y, cA.z, cA.w, cB.x, cB.y, cB.z, cB.w};
        float cn[8], hn[8];
#pragma unroll
        for (int e = 0; e < 8; ++e) {
            float ci = sigf(gv[0][e]);
            float cf = sigf(gv[1][e]);
            float cg = tanhf(gv[2][e]);
            float co = sigf(gv[3][e]);
            cn[e] = cf * cold[e] + ci * cg;
            hn[e] = co * tanhf(cn[e]);
        }
        *(float4*)(g_c + off)     = make_float4(cn[0], cn[1], cn[2], cn[3]);
        *(float4*)(g_c + off + 4) = make_float4(cn[4], cn[5], cn[6], cn[7]);

        uint32_t ph[4];
#pragma unroll
        for (int e2 = 0; e2 < 4; ++e2) {
            __half ha = __float2half_rn(hn[e2 * 2]);
            __half hb = __float2half_rn(hn[e2 * 2 + 1]);
            ph[e2] = (uint32_t)__half_as_ushort(ha) | ((uint32_t)__half_as_ushort(hb) << 16);
        }
        *(uint4*)(&g_h[wr][off]) = make_uint4(ph[0], ph[1], ph[2], ph[3]);
    }
}

// ---------------- decoder projection ----------------
__global__ __launch_bounds__(256)
void proj_kernel(int hbuf,
                 const float* __restrict__ W_out,
                 const float* __restrict__ b_out,
                 float* __restrict__ outp)
{
    int lane = threadIdx.x & 31;
    int w = threadIdx.x >> 5;
    int d = blockIdx.x * 8 + w;
    int r0 = blockIdx.y * 8;
    const __half* hp = g_h[hbuf];
    int k0 = lane * 32;

    float wv[32];
    {
        const float4* wp = (const float4*)(W_out + (size_t)d * CH + k0);
#pragma unroll
        for (int q = 0; q < 8; ++q) {
            float4 f = wp[q];
            wv[q * 4 + 0] = f.x; wv[q * 4 + 1] = f.y; wv[q * 4 + 2] = f.z; wv[q * 4 + 3] = f.w;
        }
    }
    float acc[8];
#pragma unroll
    for (int r = 0; r < 8; ++r) {
        const uint4* hq = (const uint4*)(hp + (size_t)(r0 + r) * CH + k0);
        float s = 0.0f;
#pragma unroll
        for (int q = 0; q < 4; ++q) {
            uint4 hv = hq[q];
            const __half2* h2 = (const __half2*)&hv;
#pragma unroll
            for (int e = 0; e < 4; ++e) {
                float2 a = __half22float2(h2[e]);
                int kk = q * 8 + e * 2;
                s += a.x * wv[kk] + a.y * wv[kk + 1];
            }
        }
        acc[r] = s;
    }
#pragma unroll
    for (int r = 0; r < 8; ++r) {
#pragma unroll
        for (int off = 16; off > 0; off >>= 1)
            acc[r] += __shfl_xor_sync(0xFFFFFFFFu, acc[r], off);
    }
    if (lane == 0) {
        float bo = b_out[d];
#pragma unroll
        for (int r = 0; r < 8; ++r) {
            float y = acc[r] + bo;
            int row = r0 + r;
            outp[(size_t)row * CML * CD + d] = y;
            g_xd[(size_t)row * XSTR + d] = __float2half_rn(y);
        }
    }
}

extern "C" void kernel_launch(void* const* d_in, const int* in_sizes, int n_in,
                              void* d_out, int out_size)
{
    (void)in_sizes; (void)n_in; (void)out_size;
    const float* src   = (const float*)d_in[0];
    const float* W_ih  = (const float*)d_in[1];
    const float* W_hh  = (const float*)d_in[2];
    const float* b_ih  = (const float*)d_in[3];
    const float* b_hh  = (const float*)d_in[4];
    const float* W_out = (const float*)d_in[5];
    const float* b_out = (const float*)d_in[6];
    float* out = (float*)d_out;

    static int once = 0;
    if (!once) {
        cudaFuncSetAttribute(lstm_step, cudaFuncAttributeMaxDynamicSharedMemorySize, SMEM_STEP);
        once = 1;
    }

    init_kernel<<<(CB * CH + 255) / 256, 256>>>(b_ih, b_hh);
    {
        size_t tot = (size_t)CS * CB * XSTR;
        src_split_kernel<<<(unsigned)((tot + 255) / 256), 256>>>(src);
    }
    {
        int tot = NT * NCH * 128 * 64;
        prep_w_kernel<<<(tot + 255) / 256, 256>>>(W_ih, W_hh);
    }

    dim3 sgrid(NT, CB / MT);   // 32 x 8 = 256 CTAs
    dim3 pgrid(27, CB / 8);    // 27 x 64

    int p = 0;
    for (int t = 0; t < CS; ++t) {
        lstm_step<<<sgrid, 256, SMEM_STEP>>>(0, t, p, p ^ 1);
        p ^= 1;
    }
    for (int s = 0; s < CML; ++s) {
        if (s == 0) lstm_step<<<sgrid, 256, SMEM_STEP>>>(0, CS - 1, p, p ^ 1);
        else        lstm_step<<<sgrid, 256, SMEM_STEP>>>(1, 0, p, p ^ 1);
        proj_kernel<<<pgrid, 256>>>(p ^ 1, W_out, b_out, out + (size_t)s * CD);
        p ^= 1;
    }
}